// round 2
// baseline (speedup 1.0000x reference)
#include <cuda_runtime.h>
#include <cuda_fp16.h>

#define NN 50000
#define NE 800000
#define FI 128
#define D  64
#define H  4
#define HD 256
#define ED 20

// ---------------- scratch (device globals; no runtime alloc) ----------------
__device__ float  g_h[NN * D];
__device__ float  g_xl[NN * HD];
__device__ float  g_xr[NN * HD];
__device__ float  g_eemb[NE * ED];
__device__ __half g_eeh[NE * HD];        // fp16 edge-embedding transform, CSR order
__device__ int    g_deg[NN];
__device__ int    g_cursor[NN];
__device__ int    g_rowptr[NN + 1];
__device__ int    g_srcs[NE];
__device__ int    g_eids[NE];

// packed f32x2 FMA (sm_100+)
__device__ __forceinline__ float2 ffma2(float2 a, float2 b, float2 c) {
    unsigned long long ua = *reinterpret_cast<unsigned long long*>(&a);
    unsigned long long ub = *reinterpret_cast<unsigned long long*>(&b);
    unsigned long long uc = *reinterpret_cast<unsigned long long*>(&c);
    asm("fma.rn.f32x2 %0, %1, %2, %0;" : "+l"(uc) : "l"(ua), "l"(ub));
    float2 r;
    *reinterpret_cast<unsigned long long*>(&r) = uc;
    return r;
}

// ---------------- CSR build ----------------
__global__ void k_zero() {
    int i = blockIdx.x * blockDim.x + threadIdx.x;
    if (i < NN) g_deg[i] = 0;
}

__global__ void k_hist(const int* __restrict__ ei) {
    const int* dst = ei + NE;
    int i = blockIdx.x * blockDim.x + threadIdx.x;
    if (i < NE) atomicAdd(&g_deg[dst[i]], 1);
}

__global__ void k_scan() {
    __shared__ int part[1024];
    int t = threadIdx.x;
    const int CH = 49;  // 1024*49 >= NN
    int start = t * CH;
    int s = 0;
    for (int i = 0; i < CH; i++) {
        int idx = start + i;
        if (idx < NN) s += g_deg[idx];
    }
    part[t] = s;
    __syncthreads();
    for (int off = 1; off < 1024; off <<= 1) {
        int v = (t >= off) ? part[t - off] : 0;
        __syncthreads();
        part[t] += v;
        __syncthreads();
    }
    int run = part[t] - s;  // exclusive prefix of this chunk
    for (int i = 0; i < CH; i++) {
        int idx = start + i;
        if (idx < NN) {
            g_rowptr[idx] = run;
            g_cursor[idx] = run;
            run += g_deg[idx];
        }
    }
    if (t == 0) g_rowptr[NN] = NE;
}

__global__ void k_scatter(const int* __restrict__ ei) {
    const int* src = ei;
    const int* dst = ei + NE;
    int i = blockIdx.x * blockDim.x + threadIdx.x;
    if (i < NE) {
        int d = dst[i];
        int pos = atomicAdd(&g_cursor[d], 1);
        g_srcs[pos] = src[i];
        g_eids[pos] = i;
    }
}

// ---------------- edge embedding: e_emb = relu(edge_attr @ feW + feb), CSR order
__global__ void k_eemb(const float* __restrict__ ea,
                       const float* __restrict__ feW,
                       const float* __restrict__ feb) {
    int pos = blockIdx.x * blockDim.x + threadIdx.x;
    if (pos >= NE) return;
    int e = g_eids[pos];
    float a0 = ea[2 * e], a1 = ea[2 * e + 1];
#pragma unroll
    for (int k = 0; k < ED; k++) {
        float v = fmaf(a0, __ldg(&feW[k]), fmaf(a1, __ldg(&feW[ED + k]), __ldg(&feb[k])));
        g_eemb[pos * ED + k] = v > 0.f ? v : 0.f;
    }
}

// ---------------- ee = e_emb @ We, stored fp16 (layer-invariant) ----------------
__global__ void k_ee(const float* __restrict__ We) {
    __shared__ float Ws[ED * HD];   // 20 KB
    __shared__ float es[8][ED];
    int tid = threadIdx.x;
    for (int i = tid; i < ED * HD; i += 256) Ws[i] = We[i];
    int pos0 = blockIdx.x * 8;
    for (int i = tid; i < 8 * ED; i += 256) {
        int el = i / ED, k = i % ED;
        int p = pos0 + el;
        es[el][k] = (p < NE) ? g_eemb[p * ED + k] : 0.f;
    }
    __syncthreads();
    int el = tid >> 5, lane = tid & 31;
    int pos = pos0 + el;
    if (pos >= NE) return;
    float2 a0 = {0, 0}, a1 = {0, 0}, a2 = {0, 0}, a3 = {0, 0};
    int base = lane * 8;
#pragma unroll
    for (int k = 0; k < ED; k++) {
        float a = es[el][k];
        float2 aa = {a, a};
        float4 w0 = *(const float4*)&Ws[k * HD + base];
        float4 w1 = *(const float4*)&Ws[k * HD + base + 4];
        a0 = ffma2(aa, make_float2(w0.x, w0.y), a0);
        a1 = ffma2(aa, make_float2(w0.z, w0.w), a1);
        a2 = ffma2(aa, make_float2(w1.x, w1.y), a2);
        a3 = ffma2(aa, make_float2(w1.z, w1.w), a3);
    }
    union { __half2 h[4]; uint4 u; } o;
    o.h[0] = __floats2half2_rn(a0.x, a0.y);
    o.h[1] = __floats2half2_rn(a1.x, a1.y);
    o.h[2] = __floats2half2_rn(a2.x, a2.y);
    o.h[3] = __floats2half2_rn(a3.x, a3.y);
    *(uint4*)&g_eeh[pos * HD + base] = o.u;
}

// ---------------- h0 = relu(x @ fW + fb) ----------------
__global__ void k_h0(const float* __restrict__ x,
                     const float* __restrict__ W,
                     const float* __restrict__ b) {
    __shared__ float Ws[FI * D];        // 32 KB
    __shared__ float xs[16][FI + 1];    // ~8.25 KB
    int tid = threadIdx.x;
    int row0 = blockIdx.x * 16;
    for (int i = tid; i < FI * D; i += 256) Ws[i] = W[i];
    for (int i = tid; i < 16 * FI; i += 256) {
        int r = i >> 7, c = i & 127;
        int gr = row0 + r;
        xs[r][c] = (gr < NN) ? x[gr * FI + c] : 0.f;
    }
    __syncthreads();
    int c2 = (tid & 31) * 2;
    int r0 = (tid >> 5) * 2;
    float2 acc0 = {0, 0}, acc1 = {0, 0};
    for (int k = 0; k < FI; k++) {
        float2 w = *(const float2*)&Ws[k * D + c2];
        float xa = xs[r0][k], xb = xs[r0 + 1][k];
        acc0 = ffma2(make_float2(xa, xa), w, acc0);
        acc1 = ffma2(make_float2(xb, xb), w, acc1);
    }
    float2 bv = *(const float2*)&b[c2];
    int gr = row0 + r0;
    if (gr < NN) {
        float2 o = {fmaxf(acc0.x + bv.x, 0.f), fmaxf(acc0.y + bv.y, 0.f)};
        *(float2*)&g_h[gr * D + c2] = o;
    }
    if (gr + 1 < NN) {
        float2 o = {fmaxf(acc1.x + bv.x, 0.f), fmaxf(acc1.y + bv.y, 0.f)};
        *(float2*)&g_h[(gr + 1) * D + c2] = o;
    }
}

// ---------------- layer GEMM: out = g_h @ W + b  (W: [64,256]) ----------------
__global__ void k_gemm(const float* __restrict__ W,
                       const float* __restrict__ b,
                       int which)  // 0 -> g_xl, 1 -> g_xr
{
    __shared__ float Ws[D * 128];     // 32 KB (one 128-col tile)
    __shared__ float xs[32][D + 1];   // ~8.3 KB
    int tid = threadIdx.x;
    int row0 = blockIdx.x * 32;
    int nt = blockIdx.y * 128;
    for (int i = tid; i < D * 128; i += 256) {
        int k = i >> 7, c = i & 127;
        Ws[i] = W[k * HD + nt + c];
    }
    for (int i = tid; i < 32 * D; i += 256) {
        int r = i >> 6, c = i & 63;
        int gr = row0 + r;
        xs[r][c] = (gr < NN) ? g_h[gr * D + c] : 0.f;
    }
    __syncthreads();
    int c4 = (tid & 31) * 4;
    int r0 = (tid >> 5) * 4;
    float2 acc[4][2] = {};
    for (int k = 0; k < D; k++) {
        float4 wv = *(const float4*)&Ws[k * 128 + c4];
        float2 w0 = {wv.x, wv.y}, w1 = {wv.z, wv.w};
#pragma unroll
        for (int r = 0; r < 4; r++) {
            float a = xs[r0 + r][k];
            float2 aa = {a, a};
            acc[r][0] = ffma2(aa, w0, acc[r][0]);
            acc[r][1] = ffma2(aa, w1, acc[r][1]);
        }
    }
    float* out = which ? g_xr : g_xl;
    float4 bv = *(const float4*)&b[nt + c4];
#pragma unroll
    for (int r = 0; r < 4; r++) {
        int gr = row0 + r0 + r;
        if (gr < NN) {
            float4 o = {acc[r][0].x + bv.x, acc[r][0].y + bv.y,
                        acc[r][1].x + bv.z, acc[r][1].y + bv.w};
            *(float4*)&out[gr * HD + nt + c4] = o;
        }
    }
}

// ---------------- fused per-layer GATv2: warp per dst node, online softmax ----
__global__ void k_fused(const float* __restrict__ att,
                        const float* __restrict__ bias,
                        float* __restrict__ hout)  // null -> g_h
{
    int warp = threadIdx.x >> 5;
    int v = blockIdx.x * 8 + warp;
    int lane = threadIdx.x & 31;
    if (v >= NN) return;
    float* out = hout ? hout : g_h;
    int e0 = g_rowptr[v], e1 = g_rowptr[v + 1];
    float attr[8], xrr[8];
#pragma unroll
    for (int j = 0; j < 8; j++) {
        attr[j] = __ldg(&att[j * 32 + lane]);
        xrr[j] = g_xr[v * HD + j * 32 + lane];
    }
    float m[4], l[4] = {0, 0, 0, 0}, acc[8] = {};
#pragma unroll
    for (int h = 0; h < 4; h++) m[h] = -__int_as_float(0x7f800000);
    for (int e = e0; e < e1; e++) {
        int s = g_srcs[e];
        float xlv[8], p2[4];
#pragma unroll
        for (int j = 0; j < 8; j++)
            xlv[j] = g_xl[s * HD + j * 32 + lane];
#pragma unroll
        for (int j = 0; j < 8; j++) {
            float sv = xlv[j] + xrr[j] + __half2float(g_eeh[e * HD + j * 32 + lane]);
            float lr = sv > 0.f ? sv : 0.2f * sv;
            float p = lr * attr[j];
            if (j & 1) p2[j >> 1] += p; else p2[j >> 1] = p;
        }
#pragma unroll
        for (int h = 0; h < 4; h++) {
            p2[h] += __shfl_xor_sync(0xffffffffu, p2[h], 16);
            p2[h] += __shfl_xor_sync(0xffffffffu, p2[h], 8);
            p2[h] += __shfl_xor_sync(0xffffffffu, p2[h], 4);
            p2[h] += __shfl_xor_sync(0xffffffffu, p2[h], 2);
            p2[h] += __shfl_xor_sync(0xffffffffu, p2[h], 1);
        }
#pragma unroll
        for (int h = 0; h < 4; h++) {
            float ex;
            if (p2[h] > m[h]) {          // uniform across warp (p2 broadcast)
                float sc = __expf(m[h] - p2[h]);
                l[h] = l[h] * sc + 1.0f;
                acc[2 * h] *= sc;
                acc[2 * h + 1] *= sc;
                m[h] = p2[h];
                ex = 1.0f;
            } else {
                ex = __expf(p2[h] - m[h]);
                l[h] += ex;
            }
            acc[2 * h]     = fmaf(ex, xlv[2 * h],     acc[2 * h]);
            acc[2 * h + 1] = fmaf(ex, xlv[2 * h + 1], acc[2 * h + 1]);
        }
    }
    float inv[4];
#pragma unroll
    for (int h = 0; h < 4; h++) inv[h] = (l[h] > 0.f) ? (0.25f / l[h]) : 0.f;
    float o0 = acc[0] * inv[0] + acc[2] * inv[1] + acc[4] * inv[2] + acc[6] * inv[3]
             + __ldg(&bias[lane]);
    float o1 = acc[1] * inv[0] + acc[3] * inv[1] + acc[5] * inv[2] + acc[7] * inv[3]
             + __ldg(&bias[32 + lane]);
    out[v * D + lane]      = fmaxf(o0, 0.f);
    out[v * D + 32 + lane] = fmaxf(o1, 0.f);
}

// ---------------- launch ----------------
extern "C" void kernel_launch(void* const* d_in, const int* in_sizes, int n_in,
                              void* d_out, int out_size) {
    const float* x    = (const float*)d_in[0];
    const float* ea   = (const float*)d_in[1];
    const int*   ei   = (const int*)d_in[2];
    const float* fW   = (const float*)d_in[3];
    const float* fb   = (const float*)d_in[4];
    const float* feW  = (const float*)d_in[5];
    const float* feb  = (const float*)d_in[6];
    const float* Wl   = (const float*)d_in[7];
    const float* bl   = (const float*)d_in[8];
    const float* Wr   = (const float*)d_in[9];
    const float* br   = (const float*)d_in[10];
    const float* We   = (const float*)d_in[11];
    const float* att  = (const float*)d_in[12];
    const float* bias = (const float*)d_in[13];
    float* out = (float*)d_out;

    // CSR build (once per launch)
    k_zero<<<(NN + 255) / 256, 256>>>();
    k_hist<<<(NE + 255) / 256, 256>>>(ei);
    k_scan<<<1, 1024>>>();
    k_scatter<<<(NE + 255) / 256, 256>>>(ei);

    // layer-invariant edge features
    k_eemb<<<(NE + 255) / 256, 256>>>(ea, feW, feb);
    k_ee<<<(NE + 7) / 8, 256>>>(We);

    // h0
    k_h0<<<(NN + 15) / 16, 256>>>(x, fW, fb);

    // 3 GATv2 layers (shared weights)
    dim3 gg((NN + 31) / 32, 2);
    for (int layer = 0; layer < 3; layer++) {
        k_gemm<<<gg, 256>>>(Wl, bl, 0);
        k_gemm<<<gg, 256>>>(Wr, br, 1);
        k_fused<<<(NN + 7) / 8, 256>>>(att, bias, (layer == 2) ? out : nullptr);
    }
}

// round 4
// speedup vs baseline: 2.0315x; 2.0315x over previous
#include <cuda_runtime.h>
#include <cuda_fp16.h>
#include <cuda_fp8.h>

#define NN 50000
#define NE 800000
#define FI 128
#define D  64
#define HD 256
#define ED 20
#define EESCALE 128.0f
#define EEINV   (1.0f/128.0f)

// ---------------- scratch (device globals; no runtime alloc) ----------------
// NOTE: __align__(16) is load-bearing — these are accessed with vector ld/st.
__device__ __align__(16) float         g_h[NN * D];
__device__ __align__(16) float         g_xl[NN * HD];
__device__ __align__(16) float         g_xr[NN * HD];
__device__ __align__(16) unsigned char g_ee8[(size_t)NE * HD]; // fp8 e4m3 (x128), CSR order
__device__ int    g_deg[NN];
__device__ int    g_cursor[NN];
__device__ int    g_rowptr[NN + 1];
__device__ int    g_srcs[NE];
__device__ int    g_eids[NE];

// packed f32x2 FMA (sm_100+)
__device__ __forceinline__ float2 ffma2(float2 a, float2 b, float2 c) {
    unsigned long long ua = *reinterpret_cast<unsigned long long*>(&a);
    unsigned long long ub = *reinterpret_cast<unsigned long long*>(&b);
    unsigned long long uc = *reinterpret_cast<unsigned long long*>(&c);
    asm("fma.rn.f32x2 %0, %1, %2, %0;" : "+l"(uc) : "l"(ua), "l"(ub));
    float2 r;
    *reinterpret_cast<unsigned long long*>(&r) = uc;
    return r;
}

__device__ __forceinline__ float2 fp8x2_to_f2(unsigned short v) {
    __half2_raw hr = __nv_cvt_fp8x2_to_halfraw2((__nv_fp8x2_storage_t)v, __NV_E4M3);
    __half2 h2 = *reinterpret_cast<__half2*>(&hr);
    return __half22float2(h2);
}

// ---------------- CSR build ----------------
__global__ void k_zero() {
    int i = blockIdx.x * blockDim.x + threadIdx.x;
    if (i < NN) g_deg[i] = 0;
}

__global__ void k_hist(const int* __restrict__ ei) {
    const int* dst = ei + NE;
    int i = blockIdx.x * blockDim.x + threadIdx.x;
    if (i < NE) atomicAdd(&g_deg[dst[i]], 1);
}

__global__ void k_scan() {
    __shared__ int part[1024];
    int t = threadIdx.x;
    const int CH = 49;  // 1024*49 >= NN
    int start = t * CH;
    int s = 0;
    for (int i = 0; i < CH; i++) {
        int idx = start + i;
        if (idx < NN) s += g_deg[idx];
    }
    part[t] = s;
    __syncthreads();
    for (int off = 1; off < 1024; off <<= 1) {
        int v = (t >= off) ? part[t - off] : 0;
        __syncthreads();
        part[t] += v;
        __syncthreads();
    }
    int run = part[t] - s;  // exclusive prefix of this chunk
    for (int i = 0; i < CH; i++) {
        int idx = start + i;
        if (idx < NN) {
            g_rowptr[idx] = run;
            g_cursor[idx] = run;
            run += g_deg[idx];
        }
    }
    if (t == 0) g_rowptr[NN] = NE;
}

__global__ void k_scatter(const int* __restrict__ ei) {
    const int* src = ei;
    const int* dst = ei + NE;
    int i = blockIdx.x * blockDim.x + threadIdx.x;
    if (i < NE) {
        int d = dst[i];
        int pos = atomicAdd(&g_cursor[d], 1);
        g_srcs[pos] = src[i];
        g_eids[pos] = i;
    }
}

// ---------------- ee = relu(edge_attr@feW+feb) @ We, fp8 x128, CSR order --------
// Block: 256 threads, 128 edges. Stage 1: 128 threads compute e_emb rows.
// Stage 2: thread owns 2 output cols (We cols in regs), loops 64 edges.
__global__ void k_ee(const float* __restrict__ ea,
                     const float* __restrict__ feW,
                     const float* __restrict__ feb,
                     const float* __restrict__ We) {
    __shared__ float es[128][ED + 2];   // stride 22 floats -> rows 8B aligned
    int tid = threadIdx.x;
    int pos0 = blockIdx.x * 128;
    if (tid < 128) {
        int pos = pos0 + tid;
        float a0 = 0.f, a1 = 0.f;
        if (pos < NE) {
            int e = g_eids[pos];
            a0 = ea[2 * e];
            a1 = ea[2 * e + 1];
        }
#pragma unroll
        for (int k = 0; k < ED; k++) {
            float v = fmaf(a0, __ldg(&feW[k]), fmaf(a1, __ldg(&feW[ED + k]), __ldg(&feb[k])));
            es[tid][k] = fmaxf(v, 0.f);
        }
    }
    __syncthreads();
    int half = tid >> 7;
    int c2 = (tid & 127) * 2;
    float2 w[ED];
#pragma unroll
    for (int k = 0; k < ED; k++) w[k] = *(const float2*)&We[k * HD + c2];
#pragma unroll 4
    for (int e = 0; e < 64; e++) {
        int er = half * 64 + e;
        int pos = pos0 + er;
        const float2* esr = (const float2*)es[er];
        float2 acc = {0.f, 0.f};
#pragma unroll
        for (int k2 = 0; k2 < ED / 2; k2++) {
            float2 a2 = esr[k2];
            acc = ffma2(make_float2(a2.x, a2.x), w[2 * k2], acc);
            acc = ffma2(make_float2(a2.y, a2.y), w[2 * k2 + 1], acc);
        }
        if (pos < NE) {
            float2 sc = make_float2(acc.x * EESCALE, acc.y * EESCALE);
            __nv_fp8x2_storage_t o = __nv_cvt_float2_to_fp8x2(sc, __NV_SATFINITE, __NV_E4M3);
            *(unsigned short*)&g_ee8[(size_t)pos * HD + c2] = (unsigned short)o;
        }
    }
}

// ---------------- h0 = relu(x @ fW + fb) ----------------
__global__ void k_h0(const float* __restrict__ x,
                     const float* __restrict__ W,
                     const float* __restrict__ b) {
    __shared__ float Ws[FI * D];        // 32 KB
    __shared__ float xs[16][FI + 1];
    int tid = threadIdx.x;
    int row0 = blockIdx.x * 16;
    for (int i = tid; i < FI * D; i += 256) Ws[i] = W[i];
    for (int i = tid; i < 16 * FI; i += 256) {
        int r = i >> 7, c = i & 127;
        int gr = row0 + r;
        xs[r][c] = (gr < NN) ? x[gr * FI + c] : 0.f;
    }
    __syncthreads();
    int c2 = (tid & 31) * 2;
    int r0 = (tid >> 5) * 2;
    float2 acc0 = {0, 0}, acc1 = {0, 0};
    for (int k = 0; k < FI; k++) {
        float2 w = *(const float2*)&Ws[k * D + c2];
        float xa = xs[r0][k], xb = xs[r0 + 1][k];
        acc0 = ffma2(make_float2(xa, xa), w, acc0);
        acc1 = ffma2(make_float2(xb, xb), w, acc1);
    }
    float2 bv = *(const float2*)&b[c2];
    int gr = row0 + r0;
    if (gr < NN) {
        float2 o = {fmaxf(acc0.x + bv.x, 0.f), fmaxf(acc0.y + bv.y, 0.f)};
        *(float2*)&g_h[gr * D + c2] = o;
    }
    if (gr + 1 < NN) {
        float2 o = {fmaxf(acc1.x + bv.x, 0.f), fmaxf(acc1.y + bv.y, 0.f)};
        *(float2*)&g_h[(gr + 1) * D + c2] = o;
    }
}

// ------- layer GEMM pair: xl = g_h@Wl+bl, xr = g_h@Wr+br  (W: [64,256]) -------
// grid.y: bit0 = col tile (0/1 -> cols 0-127/128-255), bit1 = which (0=l,1=r)
__global__ void k_gemm2(const float* __restrict__ Wl, const float* __restrict__ bl,
                        const float* __restrict__ Wr, const float* __restrict__ br) {
    int which = blockIdx.y >> 1;
    int nt = (blockIdx.y & 1) * 128;
    const float* W = which ? Wr : Wl;
    const float* b = which ? br : bl;
    float* out = which ? g_xr : g_xl;

    __shared__ float Ws[D * 128];       // 32 KB
    __shared__ float xt[D][64 + 1];     // transposed x tile [k][row]
    int tid = threadIdx.x;
    int row0 = blockIdx.x * 64;
    for (int i = tid; i < D * 128; i += 256) {
        int k = i >> 7, c = i & 127;
        Ws[i] = W[k * HD + nt + c];
    }
    for (int i = tid; i < 64 * D; i += 256) {
        int r = i >> 6, c = i & 63;
        int gr = row0 + r;
        xt[c][r] = (gr < NN) ? g_h[gr * D + c] : 0.f;
    }
    __syncthreads();
    int c4 = (tid & 31) * 4;
    int r0 = (tid >> 5) * 8;
    float2 acc[8][2] = {};
    for (int k = 0; k < D; k++) {
        float4 wv = *(const float4*)&Ws[k * 128 + c4];
        float2 w0 = {wv.x, wv.y}, w1 = {wv.z, wv.w};
        float a0x = xt[k][r0 + 0], a0y = xt[k][r0 + 1];
        float a0z = xt[k][r0 + 2], a0w = xt[k][r0 + 3];
        float a1x = xt[k][r0 + 4], a1y = xt[k][r0 + 5];
        float a1z = xt[k][r0 + 6], a1w = xt[k][r0 + 7];
        float ar[8] = {a0x, a0y, a0z, a0w, a1x, a1y, a1z, a1w};
#pragma unroll
        for (int r = 0; r < 8; r++) {
            float2 aa = {ar[r], ar[r]};
            acc[r][0] = ffma2(aa, w0, acc[r][0]);
            acc[r][1] = ffma2(aa, w1, acc[r][1]);
        }
    }
    float4 bv = *(const float4*)&b[nt + c4];
#pragma unroll
    for (int r = 0; r < 8; r++) {
        int gr = row0 + r0 + r;
        if (gr < NN) {
            float4 o = {acc[r][0].x + bv.x, acc[r][0].y + bv.y,
                        acc[r][1].x + bv.z, acc[r][1].y + bv.w};
            *(float4*)&out[gr * HD + nt + c4] = o;
        }
    }
}

// ---------------- fused GATv2 layer: warp per dst node, online softmax --------
// Lane L owns flat elements [L*8, L*8+8); head = L/8 (identity layout).
__global__ void k_fused(const float* __restrict__ att,
                        const float* __restrict__ bias,
                        float* __restrict__ hout)  // null -> g_h
{
    int warp = threadIdx.x >> 5;
    int v = blockIdx.x * 8 + warp;
    int lane = threadIdx.x & 31;
    if (v >= NN) return;
    int base = lane * 8;
    float4 at0 = *(const float4*)&att[base];
    float4 at1 = *(const float4*)&att[base + 4];
    const float* xrp = &g_xr[(size_t)v * HD + base];
    float4 xr0 = *(const float4*)xrp;
    float4 xr1 = *(const float4*)(xrp + 4);
    int e0 = g_rowptr[v], e1 = g_rowptr[v + 1];

    float m = -__int_as_float(0x7f800000);
    float l = 0.f;
    float acc[8] = {};
    int s = (e0 < e1) ? g_srcs[e0] : 0;
    for (int e = e0; e < e1; e++) {
        int snext = (e + 1 < e1) ? g_srcs[e + 1] : 0;
        const float4* xlp = (const float4*)&g_xl[(size_t)s * HD + base];
        float4 x0 = xlp[0];
        float4 x1 = xlp[1];
        uint2 eev = *(const uint2*)&g_ee8[(size_t)e * HD + base];
        float2 f0 = fp8x2_to_f2((unsigned short)(eev.x & 0xffffu));
        float2 f1 = fp8x2_to_f2((unsigned short)(eev.x >> 16));
        float2 f2 = fp8x2_to_f2((unsigned short)(eev.y & 0xffffu));
        float2 f3 = fp8x2_to_f2((unsigned short)(eev.y >> 16));

        float t0 = fmaf(f0.x, EEINV, x0.x + xr0.x);
        float t1 = fmaf(f0.y, EEINV, x0.y + xr0.y);
        float t2 = fmaf(f1.x, EEINV, x0.z + xr0.z);
        float t3 = fmaf(f1.y, EEINV, x0.w + xr0.w);
        float t4 = fmaf(f2.x, EEINV, x1.x + xr1.x);
        float t5 = fmaf(f2.y, EEINV, x1.y + xr1.y);
        float t6 = fmaf(f3.x, EEINV, x1.z + xr1.z);
        float t7 = fmaf(f3.y, EEINV, x1.w + xr1.w);

        float p;
        p = fmaxf(t0, 0.2f * t0) * at0.x;
        p = fmaf(fmaxf(t1, 0.2f * t1), at0.y, p);
        p = fmaf(fmaxf(t2, 0.2f * t2), at0.z, p);
        p = fmaf(fmaxf(t3, 0.2f * t3), at0.w, p);
        p = fmaf(fmaxf(t4, 0.2f * t4), at1.x, p);
        p = fmaf(fmaxf(t5, 0.2f * t5), at1.y, p);
        p = fmaf(fmaxf(t6, 0.2f * t6), at1.z, p);
        p = fmaf(fmaxf(t7, 0.2f * t7), at1.w, p);

        p += __shfl_xor_sync(0xffffffffu, p, 4);
        p += __shfl_xor_sync(0xffffffffu, p, 2);
        p += __shfl_xor_sync(0xffffffffu, p, 1);

        float mn = fmaxf(m, p);
        float c = __expf(m - mn);
        float ew = __expf(p - mn);
        l = fmaf(l, c, ew);
        m = mn;
        acc[0] = fmaf(acc[0], c, ew * x0.x);
        acc[1] = fmaf(acc[1], c, ew * x0.y);
        acc[2] = fmaf(acc[2], c, ew * x0.z);
        acc[3] = fmaf(acc[3], c, ew * x0.w);
        acc[4] = fmaf(acc[4], c, ew * x1.x);
        acc[5] = fmaf(acc[5], c, ew * x1.y);
        acc[6] = fmaf(acc[6], c, ew * x1.z);
        acc[7] = fmaf(acc[7], c, ew * x1.w);
        s = snext;
    }
    float inv = (l > 0.f) ? (0.25f / l) : 0.f;
    float r[8];
#pragma unroll
    for (int j = 0; j < 8; j++) {
        float rv = acc[j] * inv;
        rv += __shfl_xor_sync(0xffffffffu, rv, 8);
        rv += __shfl_xor_sync(0xffffffffu, rv, 16);
        r[j] = rv;
    }
    if (lane < 8) {
        float* out = hout ? hout : g_h;
        float* op = &out[v * D + lane * 8];
        const float* bp = &bias[lane * 8];
        float4 o0 = {fmaxf(r[0] + bp[0], 0.f), fmaxf(r[1] + bp[1], 0.f),
                     fmaxf(r[2] + bp[2], 0.f), fmaxf(r[3] + bp[3], 0.f)};
        float4 o1 = {fmaxf(r[4] + bp[4], 0.f), fmaxf(r[5] + bp[5], 0.f),
                     fmaxf(r[6] + bp[6], 0.f), fmaxf(r[7] + bp[7], 0.f)};
        *(float4*)op = o0;
        *(float4*)(op + 4) = o1;
    }
}

// ---------------- launch ----------------
extern "C" void kernel_launch(void* const* d_in, const int* in_sizes, int n_in,
                              void* d_out, int out_size) {
    const float* x    = (const float*)d_in[0];
    const float* ea   = (const float*)d_in[1];
    const int*   ei   = (const int*)d_in[2];
    const float* fW   = (const float*)d_in[3];
    const float* fb   = (const float*)d_in[4];
    const float* feW  = (const float*)d_in[5];
    const float* feb  = (const float*)d_in[6];
    const float* Wl   = (const float*)d_in[7];
    const float* bl   = (const float*)d_in[8];
    const float* Wr   = (const float*)d_in[9];
    const float* br   = (const float*)d_in[10];
    const float* We   = (const float*)d_in[11];
    const float* att  = (const float*)d_in[12];
    const float* bias = (const float*)d_in[13];
    float* out = (float*)d_out;

    // CSR build (once per launch)
    k_zero<<<(NN + 255) / 256, 256>>>();
    k_hist<<<(NE + 255) / 256, 256>>>(ei);
    k_scan<<<1, 1024>>>();
    k_scatter<<<(NE + 255) / 256, 256>>>(ei);

    // layer-invariant edge transform (fp8, CSR order)
    k_ee<<<(NE + 127) / 128, 256>>>(ea, feW, feb, We);

    // h0
    k_h0<<<(NN + 15) / 16, 256>>>(x, fW, fb);

    // 3 GATv2 layers (shared weights)
    dim3 gg((NN + 63) / 64, 4);
    for (int layer = 0; layer < 3; layer++) {
        k_gemm2<<<gg, 256>>>(Wl, bl, Wr, br);
        k_fused<<<(NN + 7) / 8, 256>>>(att, bias, (layer == 2) ? out : nullptr);
    }
}